// round 1
// baseline (speedup 1.0000x reference)
#include <cuda_runtime.h>
#include <cuda_bf16.h>

// Batched 1024-point FFT of real input, full complex output.
// Decomposition: 1024 = 32 x 32 four-step.
//   n = n1 + 32*n2, k = 32*k1 + k2
//   X[32*k1+k2] = FFT32_{n1->k1}( W1024^{n1*k2} * FFT32_{n2->k2}( x[n1+32*n2] ) )
// One warp per row: lane = n1 for stage 1, lane = k2 for stage 2.
// Register-resident FFT32 (fully unrolled, immediate twiddles),
// padded shared-memory 32x32 transpose between stages.

#define N_FFT 1024
#define BATCH 32768
#define WARPS_PER_BLOCK 4

__device__ __forceinline__ void fft32_reg(float* ar, float* ai) {
    // Bit-reverse permutation (compile-time swaps)
#pragma unroll
    for (int j = 0; j < 32; j++) {
        int r = ((j & 1) << 4) | ((j & 2) << 2) | (j & 4) | ((j & 8) >> 2) | ((j & 16) >> 4);
        if (r > j) {
            float t;
            t = ar[j]; ar[j] = ar[r]; ar[r] = t;
            t = ai[j]; ai[j] = ai[r]; ai[r] = t;
        }
    }
    // W_32^t for t = 0..15 : cos(-2*pi*t/32), sin(-2*pi*t/32)
    const float cw[16] = {
        1.0f,          0.98078528f,  0.92387953f,  0.83146961f,
        0.70710678f,   0.55557023f,  0.38268343f,  0.19509032f,
        0.0f,         -0.19509032f, -0.38268343f, -0.55557023f,
       -0.70710678f,  -0.83146961f, -0.92387953f, -0.98078528f };
    const float sw[16] = {
        0.0f,         -0.19509032f, -0.38268343f, -0.55557023f,
       -0.70710678f,  -0.83146961f, -0.92387953f, -0.98078528f,
       -1.0f,         -0.98078528f, -0.92387953f, -0.83146961f,
       -0.70710678f,  -0.55557023f, -0.38268343f, -0.19509032f };

#pragma unroll
    for (int s = 1; s <= 5; s++) {
        const int m = 1 << s;
        const int h = m >> 1;
        const int step = 32 >> s;   // W_m^j = W_32^(j*step)
#pragma unroll
        for (int k = 0; k < 32; k += m) {
#pragma unroll
            for (int j = 0; j < h; j++) {
                const float wr = cw[j * step];
                const float wi = sw[j * step];
                const int i0 = k + j;
                const int i1 = k + j + h;
                float tr = wr * ar[i1] - wi * ai[i1];
                float ti = wr * ai[i1] + wi * ar[i1];
                ar[i1] = ar[i0] - tr;
                ai[i1] = ai[i0] - ti;
                ar[i0] = ar[i0] + tr;
                ai[i0] = ai[i0] + ti;
            }
        }
    }
}

__global__ __launch_bounds__(WARPS_PER_BLOCK * 32)
void fft1024_kernel(const float* __restrict__ x, float* __restrict__ out) {
    __shared__ float smem[WARPS_PER_BLOCK][32 * 33];

    const int warp = threadIdx.x >> 5;
    const int lane = threadIdx.x & 31;
    const int row  = blockIdx.x * WARPS_PER_BLOCK + warp;
    if (row >= BATCH) return;

    const float* xrow = x + (size_t)row * N_FFT;

    float ar[32], ai[32];
    // lane = n1; regs over n2 (stride-32 gather; coalesced across the warp)
#pragma unroll
    for (int j = 0; j < 32; j++) {
        ar[j] = xrow[lane + 32 * j];
        ai[j] = 0.0f;
    }

    // FFT over n2 -> k2 (natural order in regs)
    fft32_reg(ar, ai);

    // Mid twiddle: W_1024^(n1 * k2), n1 = lane, k2 = reg index
#pragma unroll
    for (int j = 1; j < 32; j++) {
        float ang = -6.283185307179586e-3f * 0.9765625f * (float)(lane * j);
        // -2*pi/1024 = -0.0061359231515... ; compute precisely:
        ang = (float)(lane * j) * (-6.2831853071795864769f / 1024.0f);
        float s, c;
        __sincosf(ang, &s, &c);
        float tr = c * ar[j] - s * ai[j];
        ai[j]    = c * ai[j] + s * ar[j];
        ar[j]    = tr;
    }

    // 32x32 transpose via padded smem (conflict-free both directions)
    float* sm = smem[warp];
#pragma unroll
    for (int j = 0; j < 32; j++) sm[lane * 33 + j] = ar[j];
    __syncwarp();
#pragma unroll
    for (int j = 0; j < 32; j++) ar[j] = sm[j * 33 + lane];
    __syncwarp();
#pragma unroll
    for (int j = 0; j < 32; j++) sm[lane * 33 + j] = ai[j];
    __syncwarp();
#pragma unroll
    for (int j = 0; j < 32; j++) ai[j] = sm[j * 33 + lane];

    // FFT over n1 -> k1. lane = k2, reg index = n1 -> k1.
    fft32_reg(ar, ai);

    // X[32*k1 + k2]: reg j = k1, lane = k2 -> coalesced stores
    float* oR = out + (size_t)row * N_FFT;
    float* oI = out + (size_t)BATCH * N_FFT + (size_t)row * N_FFT;
#pragma unroll
    for (int j = 0; j < 32; j++) {
        oR[32 * j + lane] = ar[j];
        oI[32 * j + lane] = ai[j];
    }
}

extern "C" void kernel_launch(void* const* d_in, const int* in_sizes, int n_in,
                              void* d_out, int out_size) {
    const float* x = (const float*)d_in[0];
    float* out = (float*)d_out;
    const int blocks = BATCH / WARPS_PER_BLOCK;
    fft1024_kernel<<<blocks, WARPS_PER_BLOCK * 32>>>(x, out);
}

// round 2
// speedup vs baseline: 1.3430x; 1.3430x over previous
#include <cuda_runtime.h>
#include <cuda_bf16.h>

// Batched 1024-point FFT, real input, full complex output.
// Decomposition: 1024 = 16 x 16 x 4 (Cooley-Tukey, two four-step levels):
//   n = n1 + 64*n2  (n1 in [0,64), n2 in [0,16))
//   X[16*K1 + k2] = FFT64_{n1->K1}( W1024^{n1*k2} * FFT16_{n2->k2}( x[n1 + 64*n2] ) )
//   FFT64 over n1 = m1 + 4*m2:
//   X64[16*j1 + j2] = FFT4_{m1->j1}( W64^{m1*j2} * FFT16_{m2->j2}( y[m1 + 4*m2] ) )
// => final index = 256*j1 + 16*j2 + k2.
//
// 64 threads per row, 16 complex values per thread (32 floats) -> ~50 regs,
// ~2x the resident warps of the 32-per-thread version. All FFTs thread-local;
// two padded-smem exchanges (one reused buffer, 3 syncs).

#define N_FFT 1024
#define BATCH 32768
#define TPR 64            // threads per row
#define RPB 2             // rows per block
#define TPB (TPR * RPB)   // 128

__device__ __forceinline__ void fft16_reg(float* ar, float* ai) {
    // bit-reverse 4 bits (compile-time swaps)
#pragma unroll
    for (int j = 0; j < 16; j++) {
        int r = ((j & 1) << 3) | ((j & 2) << 1) | ((j & 4) >> 1) | ((j & 8) >> 3);
        if (r > j) {
            float tr = ar[j]; ar[j] = ar[r]; ar[r] = tr;
            float ti = ai[j]; ai[j] = ai[r]; ai[r] = ti;
        }
    }
    // W_16^t, t=0..7
    const float cw[8] = { 1.0f,  0.92387953f,  0.70710678f,  0.38268343f,
                          0.0f, -0.38268343f, -0.70710678f, -0.92387953f };
    const float sw[8] = { 0.0f, -0.38268343f, -0.70710678f, -0.92387953f,
                         -1.0f, -0.92387953f, -0.70710678f, -0.38268343f };
#pragma unroll
    for (int s = 1; s <= 4; s++) {
        const int m = 1 << s;
        const int h = m >> 1;
        const int step = 16 >> s;
#pragma unroll
        for (int k = 0; k < 16; k += m) {
#pragma unroll
            for (int j = 0; j < h; j++) {
                const float wr = cw[j * step];
                const float wi = sw[j * step];
                const int i0 = k + j;
                const int i1 = k + j + h;
                float tr = wr * ar[i1] - wi * ai[i1];
                float ti = wr * ai[i1] + wi * ar[i1];
                ar[i1] = ar[i0] - tr;
                ai[i1] = ai[i0] - ti;
                ar[i0] = ar[i0] + tr;
                ai[i0] = ai[i0] + ti;
            }
        }
    }
}

__global__ __launch_bounds__(TPB)
void fft1024_kernel(const float* __restrict__ x, float* __restrict__ out) {
    // one reused exchange buffer per row, 17-padded rows (conflict-free /
    // worst-case 2-way on a couple of passes)
    __shared__ float smr[RPB][64 * 17];
    __shared__ float smi[RPB][64 * 17];

    const int tid = threadIdx.x;
    const int rl  = tid >> 6;        // row within block
    const int t   = tid & 63;        // thread within row (= n1 in stage 1)
    const int row = blockIdx.x * RPB + rl;

    const float* xrow = x + (size_t)row * N_FFT;

    float ar[16], ai[16];
    // stage 1 load: n1 = t, regs over n2 (coalesced 128B per warp per instr)
#pragma unroll
    for (int n2 = 0; n2 < 16; n2++) {
        ar[n2] = xrow[t + 64 * n2];
        ai[n2] = 0.0f;
    }

    // FFT-16 over n2 -> k2 (natural order in regs)
    fft16_reg(ar, ai);

    // twiddle W_1024^{n1 * k2} = W_1024^{t * j}
#pragma unroll
    for (int j = 1; j < 16; j++) {
        float ang = (float)(t * j) * (-6.2831853071795864769f / 1024.0f);
        float s, c;
        __sincosf(ang, &s, &c);
        float tr = c * ar[j] - s * ai[j];
        ai[j]    = c * ai[j] + s * ar[j];
        ar[j]    = tr;
    }

    float* sr = smr[rl];
    float* si = smi[rl];

    // exchange 1: write (n1, k2) = (t, j)
#pragma unroll
    for (int j = 0; j < 16; j++) {
        sr[t * 17 + j] = ar[j];
        si[t * 17 + j] = ai[j];
    }
    __syncthreads();

    // stage 2: thread = (m1, k2); reads y[m1 + 4*m2][k2]
    const int m1 = t >> 4;
    const int k2 = t & 15;
#pragma unroll
    for (int m2 = 0; m2 < 16; m2++) {
        int a = (m1 + 4 * m2) * 17 + k2;
        ar[m2] = sr[a];
        ai[m2] = si[a];
    }
    __syncthreads();   // all reads done before buffer reuse

    // FFT-16 over m2 -> j2
    fft16_reg(ar, ai);

    // twiddle W_64^{m1 * j2}
#pragma unroll
    for (int j = 1; j < 16; j++) {
        float ang = (float)(m1 * j) * (-6.2831853071795864769f / 64.0f);
        float s, c;
        __sincosf(ang, &s, &c);
        float tr = c * ar[j] - s * ai[j];
        ai[j]    = c * ai[j] + s * ar[j];
        ar[j]    = tr;
    }

    // exchange 2: write (m1, j2, k2)
#pragma unroll
    for (int j = 0; j < 16; j++) {
        int a = (m1 * 16 + j) * 17 + k2;
        sr[a] = ar[j];
        si[a] = ai[j];
    }
    __syncthreads();

    // stage 3: thread = (g, k2) handles j2 = 4*g + q, q = 0..3;
    // FFT-4 over m1 -> j1; final index = 256*j1 + 16*j2 + k2
    const int g = t >> 4;
    float* oR = out + (size_t)row * N_FFT;
    float* oI = out + (size_t)BATCH * N_FFT + (size_t)row * N_FFT;

#pragma unroll
    for (int q = 0; q < 4; q++) {
        const int j2 = 4 * g + q;
        float br[4], bi[4];
#pragma unroll
        for (int mm = 0; mm < 4; mm++) {
            int a = (mm * 16 + j2) * 17 + k2;
            br[mm] = sr[a];
            bi[mm] = si[a];
        }
        float t0r = br[0] + br[2], t0i = bi[0] + bi[2];
        float t1r = br[0] - br[2], t1i = bi[0] - bi[2];
        float t2r = br[1] + br[3], t2i = bi[1] + bi[3];
        float t3r = br[1] - br[3], t3i = bi[1] - bi[3];

        const int base = 16 * j2 + k2;
        // j1 = 0: t0 + t2
        oR[base]       = t0r + t2r;  oI[base]       = t0i + t2i;
        // j1 = 1: t1 - i*t3
        oR[base + 256] = t1r + t3i;  oI[base + 256] = t1i - t3r;
        // j1 = 2: t0 - t2
        oR[base + 512] = t0r - t2r;  oI[base + 512] = t0i - t2i;
        // j1 = 3: t1 + i*t3
        oR[base + 768] = t1r - t3i;  oI[base + 768] = t1i + t3r;
    }
}

extern "C" void kernel_launch(void* const* d_in, const int* in_sizes, int n_in,
                              void* d_out, int out_size) {
    const float* x = (const float*)d_in[0];
    float* out = (float*)d_out;
    const int blocks = BATCH / RPB;   // 16384
    fft1024_kernel<<<blocks, TPB>>>(x, out);
}

// round 3
// speedup vs baseline: 1.4082x; 1.0486x over previous
#include <cuda_runtime.h>
#include <cuda_bf16.h>

// Batched 1024-point FFT, real input, complex output (real block then imag block).
// 1024 = 16(n2) x [64 = 4(m1) x 16(m2)], same index math as the passing R2 kernel:
//   final index = 256*j1 + 16*j2 + k2
// 64 threads/row, 16 complex per thread. float2 smem exchanges (conflict-free
// strides), stage-3 restructured for LDS.128 reads + STG.128 coalesced stores,
// twiddles by one sincos + complex recurrence per stage.

#define N_FFT 1024
#define BATCH 32768
#define TPR 64
#define RPB 2
#define TPB (TPR * RPB)

#define S1 17   // float2 stride, exchange 1
#define S2 18   // float2 stride, exchange 2 (even -> 16B-aligned LDS.128)

__device__ __forceinline__ void fft16_reg(float* ar, float* ai) {
#pragma unroll
    for (int j = 0; j < 16; j++) {
        int r = ((j & 1) << 3) | ((j & 2) << 1) | ((j & 4) >> 1) | ((j & 8) >> 3);
        if (r > j) {
            float tr = ar[j]; ar[j] = ar[r]; ar[r] = tr;
            float ti = ai[j]; ai[j] = ai[r]; ai[r] = ti;
        }
    }
    const float cw[8] = { 1.0f,  0.92387953f,  0.70710678f,  0.38268343f,
                          0.0f, -0.38268343f, -0.70710678f, -0.92387953f };
    const float sw[8] = { 0.0f, -0.38268343f, -0.70710678f, -0.92387953f,
                         -1.0f, -0.92387953f, -0.70710678f, -0.38268343f };
#pragma unroll
    for (int s = 1; s <= 4; s++) {
        const int m = 1 << s;
        const int h = m >> 1;
        const int step = 16 >> s;
#pragma unroll
        for (int k = 0; k < 16; k += m) {
#pragma unroll
            for (int j = 0; j < h; j++) {
                const float wr = cw[j * step];
                const float wi = sw[j * step];
                const int i0 = k + j;
                const int i1 = k + j + h;
                float tr = wr * ar[i1] - wi * ai[i1];
                float ti = wr * ai[i1] + wi * ar[i1];
                ar[i1] = ar[i0] - tr;
                ai[i1] = ai[i0] - ti;
                ar[i0] = ar[i0] + tr;
                ai[i0] = ai[i0] + ti;
            }
        }
    }
}

// multiply regs j=1..15 by w^j via recurrence (w given by angle step)
__device__ __forceinline__ void twiddle15(float* ar, float* ai, float step_ang) {
    float ws, wc;
    __sincosf(step_ang, &ws, &wc);
    float cr = wc, ci = ws;   // w^1
#pragma unroll
    for (int j = 1; j < 16; j++) {
        float tr = cr * ar[j] - ci * ai[j];
        float ti = cr * ai[j] + ci * ar[j];
        ar[j] = tr; ai[j] = ti;
        // cur *= w
        float nr = cr * wc - ci * ws;
        float ni = cr * ws + ci * wc;
        cr = nr; ci = ni;
    }
}

__global__ __launch_bounds__(TPB)
void fft1024_kernel(const float* __restrict__ x, float* __restrict__ out) {
    __shared__ float2 smem[RPB][64 * S2];   // reused for both exchanges

    const int tid = threadIdx.x;
    const int rl  = tid >> 6;
    const int t   = tid & 63;
    const int row = blockIdx.x * RPB + rl;

    const float* xrow = x + (size_t)row * N_FFT;
    float2* sm = smem[rl];

    float ar[16], ai[16];
#pragma unroll
    for (int n2 = 0; n2 < 16; n2++) {
        ar[n2] = xrow[t + 64 * n2];
        ai[n2] = 0.0f;
    }

    // FFT-16 over n2 -> k2
    fft16_reg(ar, ai);

    // W_1024^{t * k2}
    twiddle15(ar, ai, (float)t * (-6.2831853071795864769f / 1024.0f));

    // exchange 1: [n1 = t][k2 = j], stride S1 (conflict-free)
#pragma unroll
    for (int j = 0; j < 16; j++)
        sm[t * S1 + j] = make_float2(ar[j], ai[j]);
    __syncthreads();

    // stage 2: thread = (m1, k2); n1 = m1 + 4*m2
    const int m1 = t >> 4;
    const int k2 = t & 15;
#pragma unroll
    for (int m2 = 0; m2 < 16; m2++) {
        float2 v = sm[(m1 + 4 * m2) * S1 + k2];
        ar[m2] = v.x; ai[m2] = v.y;
    }
    __syncthreads();   // reads done before buffer reuse

    // FFT-16 over m2 -> j2
    fft16_reg(ar, ai);

    // W_64^{m1 * j2}
    twiddle15(ar, ai, (float)m1 * (-6.2831853071795864769f / 64.0f));

    // exchange 2: [(m1*16 + j2)][k2], stride S2 (even -> stage-3 LDS.128 aligned)
#pragma unroll
    for (int j = 0; j < 16; j++)
        sm[(m1 * 16 + j) * S2 + k2] = make_float2(ar[j], ai[j]);
    __syncthreads();

    // stage 3: thread = (j2 = t>>2, c = t&3) handles k2 in {4c..4c+3}
    // FFT-4 over m1 -> j1, final index = 256*j1 + 16*j2 + k2
    const int j2 = t >> 2;
    const int c  = t & 3;

    float br[4][4], bi[4][4];   // [m1][d], d = k2 - 4c
#pragma unroll
    for (int mm = 0; mm < 4; mm++) {
        const float4* p = (const float4*)(sm + (mm * 16 + j2) * S2 + 4 * c);
        float4 A = p[0];   // (r0, i0, r1, i1)
        float4 B = p[1];   // (r2, i2, r3, i3)
        br[mm][0] = A.x; bi[mm][0] = A.y;
        br[mm][1] = A.z; bi[mm][1] = A.w;
        br[mm][2] = B.x; bi[mm][2] = B.y;
        br[mm][3] = B.z; bi[mm][3] = B.w;
    }

    float oRr[4][4], oIr[4][4];  // [j1][d]
#pragma unroll
    for (int d = 0; d < 4; d++) {
        float t0r = br[0][d] + br[2][d], t0i = bi[0][d] + bi[2][d];
        float t1r = br[0][d] - br[2][d], t1i = bi[0][d] - bi[2][d];
        float t2r = br[1][d] + br[3][d], t2i = bi[1][d] + bi[3][d];
        float t3r = br[1][d] - br[3][d], t3i = bi[1][d] - bi[3][d];
        oRr[0][d] = t0r + t2r;  oIr[0][d] = t0i + t2i;
        oRr[1][d] = t1r + t3i;  oIr[1][d] = t1i - t3r;
        oRr[2][d] = t0r - t2r;  oIr[2][d] = t0i - t2i;
        oRr[3][d] = t1r - t3i;  oIr[3][d] = t1i + t3r;
    }

    float* oR = out + (size_t)row * N_FFT;
    float* oI = out + (size_t)BATCH * N_FFT + (size_t)row * N_FFT;
    const int base = 16 * j2 + 4 * c;
#pragma unroll
    for (int j1 = 0; j1 < 4; j1++) {
        *(float4*)(oR + 256 * j1 + base) =
            make_float4(oRr[j1][0], oRr[j1][1], oRr[j1][2], oRr[j1][3]);
        *(float4*)(oI + 256 * j1 + base) =
            make_float4(oIr[j1][0], oIr[j1][1], oIr[j1][2], oIr[j1][3]);
    }
}

extern "C" void kernel_launch(void* const* d_in, const int* in_sizes, int n_in,
                              void* d_out, int out_size) {
    const float* x = (const float*)d_in[0];
    float* out = (float*)d_out;
    fft1024_kernel<<<BATCH / RPB, TPB>>>(x, out);
}

// round 4
// speedup vs baseline: 5.9940x; 4.2565x over previous
#include <cuda_runtime.h>
#include <cuda_bf16.h>

// Batched 1024-point FFT, real input, complex output ([real block][imag block]).
// 1024 = 16(n2) x [64 = 4(m1) x 16(m2)]; final index = 256*j1 + 16*j2 + k2.
// 64 threads/row, 16 complex per thread.
// R4: cp.async-staged input (kills front-batched LDG queue contention),
//     radix-4 FFT16 with real-input specialization for stage A,
//     parallel sincos twiddles (no serial recurrence).

#define N_FFT 1024
#define BATCH 32768
#define TPR 64
#define RPB 2
#define TPB (TPR * RPB)

#define S1 17   // float2 stride, exchange 1
#define S2 18   // float2 stride, exchange 2 (even -> 16B-aligned LDS.128)

// cos/sin(-2*pi*t/16), t = 0..15
#define W16_TABLES \
    const float C[16] = { 1.0f,  0.92387953f,  0.70710678f,  0.38268343f, \
                          0.0f, -0.38268343f, -0.70710678f, -0.92387953f, \
                         -1.0f, -0.92387953f, -0.70710678f, -0.38268343f, \
                          0.0f,  0.38268343f,  0.70710678f,  0.92387953f }; \
    const float S[16] = { 0.0f, -0.38268343f, -0.70710678f, -0.92387953f, \
                         -1.0f, -0.92387953f, -0.70710678f, -0.38268343f, \
                          0.0f,  0.38268343f,  0.70710678f,  0.92387953f, \
                          1.0f,  0.92387953f,  0.70710678f,  0.38268343f };

// Complex FFT-16, natural in/out. n = a + 4b; X[4k1+k2].
__device__ __forceinline__ void fft16c(float* ar, float* ai) {
    W16_TABLES
    float zr[16], zi[16];
    // a = 0 (no twiddle)
    {
        float t0r = ar[0] + ar[8],  t0i = ai[0] + ai[8];
        float t1r = ar[0] - ar[8],  t1i = ai[0] - ai[8];
        float t2r = ar[4] + ar[12], t2i = ai[4] + ai[12];
        float t3r = ar[4] - ar[12], t3i = ai[4] - ai[12];
        zr[0] = t0r + t2r; zi[0] = t0i + t2i;
        zr[1] = t1r + t3i; zi[1] = t1i - t3r;
        zr[2] = t0r - t2r; zi[2] = t0i - t2i;
        zr[3] = t1r - t3i; zi[3] = t1i + t3r;
    }
#pragma unroll
    for (int a = 1; a < 4; a++) {
        float t0r = ar[a] + ar[a+8],  t0i = ai[a] + ai[a+8];
        float t1r = ar[a] - ar[a+8],  t1i = ai[a] - ai[a+8];
        float t2r = ar[a+4] + ar[a+12], t2i = ai[a+4] + ai[a+12];
        float t3r = ar[a+4] - ar[a+12], t3i = ai[a+4] - ai[a+12];
        float y1r = t1r + t3i, y1i = t1i - t3r;
        float y2r = t0r - t2r, y2i = t0i - t2i;
        float y3r = t1r - t3i, y3i = t1i + t3r;
        zr[4*a+0] = t0r + t2r; zi[4*a+0] = t0i + t2i;
        { const float c = C[a], s = S[a];
          zr[4*a+1] = c*y1r - s*y1i; zi[4*a+1] = c*y1i + s*y1r; }
        { const float c = C[(2*a)&15], s = S[(2*a)&15];
          zr[4*a+2] = c*y2r - s*y2i; zi[4*a+2] = c*y2i + s*y2r; }
        { const float c = C[(3*a)&15], s = S[(3*a)&15];
          zr[4*a+3] = c*y3r - s*y3i; zi[4*a+3] = c*y3i + s*y3r; }
    }
#pragma unroll
    for (int k2 = 0; k2 < 4; k2++) {
        float t0r = zr[k2]   + zr[k2+8],  t0i = zi[k2]   + zi[k2+8];
        float t1r = zr[k2]   - zr[k2+8],  t1i = zi[k2]   - zi[k2+8];
        float t2r = zr[k2+4] + zr[k2+12], t2i = zi[k2+4] + zi[k2+12];
        float t3r = zr[k2+4] - zr[k2+12], t3i = zi[k2+4] - zi[k2+12];
        ar[k2]    = t0r + t2r;  ai[k2]    = t0i + t2i;
        ar[k2+4]  = t1r + t3i;  ai[k2+4]  = t1i - t3r;
        ar[k2+8]  = t0r - t2r;  ai[k2+8]  = t0i - t2i;
        ar[k2+12] = t1r - t3i;  ai[k2+12] = t1i + t3r;
    }
}

// Real-input FFT-16: ar holds real x[0..15] on entry (ai ignored), natural out.
__device__ __forceinline__ void fft16_real(float* ar, float* ai) {
    W16_TABLES
    float zr[16], zi[16];
    // a = 0: no twiddle
    {
        float t0 = ar[0] + ar[8],  t1 = ar[0] - ar[8];
        float t2 = ar[4] + ar[12], t3 = ar[4] - ar[12];
        zr[0] = t0 + t2;
        zr[1] = t1;      zi[1] = -t3;
        zr[2] = t0 - t2; zi[2] = 0.0f;
        zr[3] = t1;      zi[3] = t3;
    }
#pragma unroll
    for (int a = 1; a < 4; a++) {
        float t0 = ar[a] + ar[a+8],   t1 = ar[a] - ar[a+8];
        float t2 = ar[a+4] + ar[a+12], t3 = ar[a+4] - ar[a+12];
        zr[4*a+0] = t0 + t2;
        // y1 = (t1, -t3) * W16^a
        { const float c = C[a], s = S[a];
          zr[4*a+1] = c*t1 + s*t3; zi[4*a+1] = s*t1 - c*t3; }
        // y2 = (t0-t2, 0) * W16^{2a}
        { const float c = C[(2*a)&15], s = S[(2*a)&15];
          float y2 = t0 - t2;
          zr[4*a+2] = c*y2; zi[4*a+2] = s*y2; }
        // y3 = (t1, t3) * W16^{3a}
        { const float c = C[(3*a)&15], s = S[(3*a)&15];
          zr[4*a+3] = c*t1 - s*t3; zi[4*a+3] = s*t1 + c*t3; }
    }
    // outer k2 = 0: all-real column
    {
        float t0 = zr[0] + zr[8],  t1 = zr[0] - zr[8];
        float t2 = zr[4] + zr[12], t3 = zr[4] - zr[12];
        ar[0]  = t0 + t2; ai[0]  = 0.0f;
        ar[4]  = t1;      ai[4]  = -t3;
        ar[8]  = t0 - t2; ai[8]  = 0.0f;
        ar[12] = t1;      ai[12] = t3;
    }
#pragma unroll
    for (int k2 = 1; k2 < 4; k2++) {
        float t0r = zr[k2]   + zr[k2+8],  t0i = zi[k2]   + zi[k2+8];
        float t1r = zr[k2]   - zr[k2+8],  t1i = zi[k2]   - zi[k2+8];
        float t2r = zr[k2+4] + zr[k2+12], t2i = zi[k2+4] + zi[k2+12];
        float t3r = zr[k2+4] - zr[k2+12], t3i = zi[k2+4] - zi[k2+12];
        ar[k2]    = t0r + t2r;  ai[k2]    = t0i + t2i;
        ar[k2+4]  = t1r + t3i;  ai[k2+4]  = t1i - t3r;
        ar[k2+8]  = t0r - t2r;  ai[k2+8]  = t0i - t2i;
        ar[k2+12] = t1r - t3i;  ai[k2+12] = t1i + t3r;
    }
}

// Multiply regs j=1..15 by w^j, w = exp(i*base); independent sincos per j.
__device__ __forceinline__ void twiddle15p(float* ar, float* ai, float base) {
#pragma unroll
    for (int j = 1; j < 16; j++) {
        float s, c;
        __sincosf(base * (float)j, &s, &c);
        float tr = c * ar[j] - s * ai[j];
        ai[j]    = c * ai[j] + s * ar[j];
        ar[j]    = tr;
    }
}

__global__ __launch_bounds__(TPB)
void fft1024_kernel(const float* __restrict__ x, float* __restrict__ out) {
    __shared__ __align__(16) float2 smem[RPB][64 * S2];

    const int tid = threadIdx.x;
    const int rl  = tid >> 6;
    const int t   = tid & 63;
    const int row = blockIdx.x * RPB + rl;

    float2* sm  = smem[rl];
    float*  lin = (float*)sm;

    // ---- stage input row into smem via cp.async (coalesced, low MLP) ----
    {
        const float4* xrow4 = (const float4*)(x + (size_t)row * N_FFT);
        unsigned sbase = (unsigned)__cvta_generic_to_shared(lin);
#pragma unroll
        for (int c = 0; c < 4; c++) {
            int f = t + 64 * c;
            asm volatile("cp.async.cg.shared.global [%0], [%1], 16;\n"
                         :: "r"(sbase + f * 16), "l"(xrow4 + f));
        }
        asm volatile("cp.async.commit_group;\n");
        asm volatile("cp.async.wait_group 0;\n");
    }
    __syncthreads();

    float ar[16], ai[16];
#pragma unroll
    for (int n2 = 0; n2 < 16; n2++) ar[n2] = lin[t + 64 * n2];
    __syncthreads();   // all reads done before exchange-1 overwrites buffer

    // stage A: FFT-16 over n2 -> k2 (real input), twiddle W_1024^{t*k2}
    fft16_real(ar, ai);
    twiddle15p(ar, ai, (float)t * (-6.2831853071795864769f / 1024.0f));

    // exchange 1: [n1 = t][k2 = j]
#pragma unroll
    for (int j = 0; j < 16; j++)
        sm[t * S1 + j] = make_float2(ar[j], ai[j]);
    __syncthreads();

    // stage B: thread = (m1, k2); n1 = m1 + 4*m2
    const int m1 = t >> 4;
    const int k2 = t & 15;
#pragma unroll
    for (int m2 = 0; m2 < 16; m2++) {
        float2 v = sm[(m1 + 4 * m2) * S1 + k2];
        ar[m2] = v.x; ai[m2] = v.y;
    }
    __syncthreads();

    fft16c(ar, ai);
    twiddle15p(ar, ai, (float)m1 * (-6.2831853071795864769f / 64.0f));

    // exchange 2: [(m1*16 + j2)][k2]
#pragma unroll
    for (int j = 0; j < 16; j++)
        sm[(m1 * 16 + j) * S2 + k2] = make_float2(ar[j], ai[j]);
    __syncthreads();

    // stage C: thread = (j2 = t>>2, c = t&3) handles k2 in {4c..4c+3};
    // FFT-4 over m1 -> j1, final index = 256*j1 + 16*j2 + k2
    const int j2 = t >> 2;
    const int c  = t & 3;

    float br[4][4], bi[4][4];
#pragma unroll
    for (int mm = 0; mm < 4; mm++) {
        const float4* p = (const float4*)(sm + (mm * 16 + j2) * S2 + 4 * c);
        float4 A = p[0];
        float4 B = p[1];
        br[mm][0] = A.x; bi[mm][0] = A.y;
        br[mm][1] = A.z; bi[mm][1] = A.w;
        br[mm][2] = B.x; bi[mm][2] = B.y;
        br[mm][3] = B.z; bi[mm][3] = B.w;
    }

    float oRr[4][4], oIr[4][4];
#pragma unroll
    for (int d = 0; d < 4; d++) {
        float t0r = br[0][d] + br[2][d], t0i = bi[0][d] + bi[2][d];
        float t1r = br[0][d] - br[2][d], t1i = bi[0][d] - bi[2][d];
        float t2r = br[1][d] + br[3][d], t2i = bi[1][d] + bi[3][d];
        float t3r = br[1][d] - br[3][d], t3i = bi[1][d] - bi[3][d];
        oRr[0][d] = t0r + t2r;  oIr[0][d] = t0i + t2i;
        oRr[1][d] = t1r + t3i;  oIr[1][d] = t1i - t3r;
        oRr[2][d] = t0r - t2r;  oIr[2][d] = t0i - t2i;
        oRr[3][d] = t1r - t3i;  oIr[3][d] = t1i + t3r;
    }

    float* oR = out + (size_t)row * N_FFT;
    float* oI = out + (size_t)BATCH * N_FFT + (size_t)row * N_FFT;
    const int base = 16 * j2 + 4 * c;
#pragma unroll
    for (int j1 = 0; j1 < 4; j1++) {
        *(float4*)(oR + 256 * j1 + base) =
            make_float4(oRr[j1][0], oRr[j1][1], oRr[j1][2], oRr[j1][3]);
        *(float4*)(oI + 256 * j1 + base) =
            make_float4(oIr[j1][0], oIr[j1][1], oIr[j1][2], oIr[j1][3]);
    }
}

extern "C" void kernel_launch(void* const* d_in, const int* in_sizes, int n_in,
                              void* d_out, int out_size) {
    const float* x = (const float*)d_in[0];
    float* out = (float*)d_out;
    fft1024_kernel<<<BATCH / RPB, TPB>>>(x, out);
}

// round 5
// speedup vs baseline: 6.0210x; 1.0045x over previous
#include <cuda_runtime.h>
#include <cuda_bf16.h>

// Batched 1024-point FFT, real input, complex output ([real block][imag block]).
// R5: two real rows per complex FFT (z = xa + i*xb), Hermitian unpack at the end.
// 1024 = 16(n2) x [64 = 4(m1) x 16(m2)]; Z index = 256*j1 + 16*j2 + k2.
// 64 threads per row-pair, 16 complex per thread. One reused smem buffer per
// pair: cp.async staging -> ex1 -> ex2 -> ex3(unpack), conflict-free strides.

#define N_FFT 1024
#define BATCH 32768
#define TPR 64            // threads per row-pair
#define PPB 2             // pairs per block
#define TPB (TPR * PPB)   // 128

#define S1 17             // float2 stride for ex1/ex2 row exchanges
#define BUFSZ 1152        // float2 per pair buffer (>= 64*S1=1088, >=1024 staging, >=phys(1023)=1086)

// phys index for ex3: pad 1 float2 per 16 complex (conflict-free unpack passes)
#define PHYS(k) ((k) + ((k) >> 4))

// cos/sin(-2*pi*t/16), t = 0..15
#define W16_TABLES \
    const float C[16] = { 1.0f,  0.92387953f,  0.70710678f,  0.38268343f, \
                          0.0f, -0.38268343f, -0.70710678f, -0.92387953f, \
                         -1.0f, -0.92387953f, -0.70710678f, -0.38268343f, \
                          0.0f,  0.38268343f,  0.70710678f,  0.92387953f }; \
    const float S[16] = { 0.0f, -0.38268343f, -0.70710678f, -0.92387953f, \
                         -1.0f, -0.92387953f, -0.70710678f, -0.38268343f, \
                          0.0f,  0.38268343f,  0.70710678f,  0.92387953f, \
                          1.0f,  0.92387953f,  0.70710678f,  0.38268343f };

// Complex FFT-16, natural order in/out (radix-4 x radix-4).
__device__ __forceinline__ void fft16c(float* ar, float* ai) {
    W16_TABLES
    float zr[16], zi[16];
    {
        float t0r = ar[0] + ar[8],  t0i = ai[0] + ai[8];
        float t1r = ar[0] - ar[8],  t1i = ai[0] - ai[8];
        float t2r = ar[4] + ar[12], t2i = ai[4] + ai[12];
        float t3r = ar[4] - ar[12], t3i = ai[4] - ai[12];
        zr[0] = t0r + t2r; zi[0] = t0i + t2i;
        zr[1] = t1r + t3i; zi[1] = t1i - t3r;
        zr[2] = t0r - t2r; zi[2] = t0i - t2i;
        zr[3] = t1r - t3i; zi[3] = t1i + t3r;
    }
#pragma unroll
    for (int a = 1; a < 4; a++) {
        float t0r = ar[a] + ar[a+8],  t0i = ai[a] + ai[a+8];
        float t1r = ar[a] - ar[a+8],  t1i = ai[a] - ai[a+8];
        float t2r = ar[a+4] + ar[a+12], t2i = ai[a+4] + ai[a+12];
        float t3r = ar[a+4] - ar[a+12], t3i = ai[a+4] - ai[a+12];
        float y1r = t1r + t3i, y1i = t1i - t3r;
        float y2r = t0r - t2r, y2i = t0i - t2i;
        float y3r = t1r - t3i, y3i = t1i + t3r;
        zr[4*a+0] = t0r + t2r; zi[4*a+0] = t0i + t2i;
        { const float c = C[a], s = S[a];
          zr[4*a+1] = c*y1r - s*y1i; zi[4*a+1] = c*y1i + s*y1r; }
        { const float c = C[(2*a)&15], s = S[(2*a)&15];
          zr[4*a+2] = c*y2r - s*y2i; zi[4*a+2] = c*y2i + s*y2r; }
        { const float c = C[(3*a)&15], s = S[(3*a)&15];
          zr[4*a+3] = c*y3r - s*y3i; zi[4*a+3] = c*y3i + s*y3r; }
    }
#pragma unroll
    for (int k2 = 0; k2 < 4; k2++) {
        float t0r = zr[k2]   + zr[k2+8],  t0i = zi[k2]   + zi[k2+8];
        float t1r = zr[k2]   - zr[k2+8],  t1i = zi[k2]   - zi[k2+8];
        float t2r = zr[k2+4] + zr[k2+12], t2i = zi[k2+4] + zi[k2+12];
        float t3r = zr[k2+4] - zr[k2+12], t3i = zi[k2+4] - zi[k2+12];
        ar[k2]    = t0r + t2r;  ai[k2]    = t0i + t2i;
        ar[k2+4]  = t1r + t3i;  ai[k2+4]  = t1i - t3r;
        ar[k2+8]  = t0r - t2r;  ai[k2+8]  = t0i - t2i;
        ar[k2+12] = t1r - t3i;  ai[k2+12] = t1i + t3r;
    }
}

// Multiply regs j=1..15 by w^j, w = exp(i*base); independent sincos per j.
__device__ __forceinline__ void twiddle15p(float* ar, float* ai, float base) {
#pragma unroll
    for (int j = 1; j < 16; j++) {
        float s, c;
        __sincosf(base * (float)j, &s, &c);
        float tr = c * ar[j] - s * ai[j];
        ai[j]    = c * ai[j] + s * ar[j];
        ar[j]    = tr;
    }
}

__global__ __launch_bounds__(TPB)
void fft1024_kernel(const float* __restrict__ x, float* __restrict__ out) {
    __shared__ __align__(16) float2 smem[PPB][BUFSZ];

    const int tid  = threadIdx.x;
    const int pl   = tid >> 6;          // pair within block
    const int t    = tid & 63;          // thread within pair
    const int pair = blockIdx.x * PPB + pl;
    const int rowA = 2 * pair;          // rows (2p, 2p+1)

    float2* sm  = smem[pl];
    float*  lin = (float*)sm;

    // ---- stage rows a,b into smem via cp.async (coalesced, bounded MLP) ----
    {
        const float4* xa4 = (const float4*)(x + (size_t)rowA * N_FFT);
        unsigned sbase = (unsigned)__cvta_generic_to_shared(lin);
#pragma unroll
        for (int c = 0; c < 8; c++) {               // c<4: row a, c>=4: row b
            int f = t + 64 * c;                     // float4 index within 2 rows
            asm volatile("cp.async.cg.shared.global [%0], [%1], 16;\n"
                         :: "r"(sbase + f * 16), "l"(xa4 + f));
        }
        asm volatile("cp.async.commit_group;\n");
        asm volatile("cp.async.wait_group 0;\n");
    }
    __syncthreads();

    // z[n] = xa[n] + i*xb[n]; lane = n1 = t, regs over n2
    float ar[16], ai[16];
#pragma unroll
    for (int n2 = 0; n2 < 16; n2++) {
        ar[n2] = lin[t + 64 * n2];
        ai[n2] = lin[1024 + t + 64 * n2];
    }
    __syncthreads();   // reads done before ex1 overwrites

    // stage A: FFT-16 over n2 -> k2, twiddle W_1024^{t*k2}
    fft16c(ar, ai);
    twiddle15p(ar, ai, (float)t * (-6.2831853071795864769f / 1024.0f));

    // ex1: [n1 = t][k2 = j]
#pragma unroll
    for (int j = 0; j < 16; j++)
        sm[t * S1 + j] = make_float2(ar[j], ai[j]);
    __syncthreads();

    // stage B: thread = (m1, k2); n1 = m1 + 4*m2
    const int m1 = t >> 4;
    const int k2 = t & 15;
#pragma unroll
    for (int m2 = 0; m2 < 16; m2++) {
        float2 v = sm[(m1 + 4 * m2) * S1 + k2];
        ar[m2] = v.x; ai[m2] = v.y;
    }
    __syncthreads();

    fft16c(ar, ai);
    twiddle15p(ar, ai, (float)m1 * (-6.2831853071795864769f / 64.0f));

    // ex2: [(m1*16 + j2)][k2]
#pragma unroll
    for (int j = 0; j < 16; j++)
        sm[(m1 * 16 + j) * S1 + k2] = make_float2(ar[j], ai[j]);
    __syncthreads();

    // stage C: thread = (j2 = t>>2, c = t&3) handles k2 in {4c..4c+3};
    // FFT-4 over m1 -> j1; write Z[k] to ex3 at PHYS(k), k = 256*j1+16*j2+4c+d
    {
        const int j2 = t >> 2;
        const int cq = t & 3;
        float br[4][4], bi[4][4];
#pragma unroll
        for (int mm = 0; mm < 4; mm++) {
#pragma unroll
            for (int d = 0; d < 4; d++) {
                float2 v = sm[(mm * 16 + j2) * S1 + 4 * cq + d];
                br[mm][d] = v.x; bi[mm][d] = v.y;
            }
        }
        __syncthreads();   // ex2 reads done before ex3 overwrites

#pragma unroll
        for (int d = 0; d < 4; d++) {
            float t0r = br[0][d] + br[2][d], t0i = bi[0][d] + bi[2][d];
            float t1r = br[0][d] - br[2][d], t1i = bi[0][d] - bi[2][d];
            float t2r = br[1][d] + br[3][d], t2i = bi[1][d] + bi[3][d];
            float t3r = br[1][d] - br[3][d], t3i = bi[1][d] - bi[3][d];
            const int kb = 16 * j2 + 4 * cq + d;
            sm[PHYS(kb      )] = make_float2(t0r + t2r, t0i + t2i);
            sm[PHYS(kb + 256)] = make_float2(t1r + t3i, t1i - t3r);
            sm[PHYS(kb + 512)] = make_float2(t0r - t2r, t0i - t2i);
            sm[PHYS(kb + 768)] = make_float2(t1r - t3i, t1i + t3r);
        }
    }
    __syncthreads();

    // ---- Hermitian unpack + streaming stores ----
    // thread t handles k = 256*u + 4*t + d, u = 0..3, d = 0..3 (float4 coalesced)
    float* oRa = out + (size_t)rowA * N_FFT;
    float* oIa = out + (size_t)BATCH * N_FFT + (size_t)rowA * N_FFT;
    float* oRb = oRa + N_FFT;
    float* oIb = oIa + N_FFT;

#pragma unroll
    for (int u = 0; u < 4; u++) {
        const int k0 = 256 * u + 4 * t;
        float4 xar, xai, xbr, xbi;
        float* pxar = &xar.x; float* pxai = &xai.x;
        float* pxbr = &xbr.x; float* pxbi = &xbi.x;
#pragma unroll
        for (int d = 0; d < 4; d++) {
            const int k  = k0 + d;
            const int km = (N_FFT - k) & (N_FFT - 1);
            float2 Z = sm[PHYS(k)];
            float2 M = sm[PHYS(km)];
            pxar[d] = 0.5f * (Z.x + M.x);
            pxai[d] = 0.5f * (Z.y - M.y);
            pxbr[d] = 0.5f * (Z.y + M.y);
            pxbi[d] = 0.5f * (M.x - Z.x);
        }
        __stcs((float4*)(oRa + k0), xar);
        __stcs((float4*)(oIa + k0), xai);
        __stcs((float4*)(oRb + k0), xbr);
        __stcs((float4*)(oIb + k0), xbi);
    }
}

extern "C" void kernel_launch(void* const* d_in, const int* in_sizes, int n_in,
                              void* d_out, int out_size) {
    const float* x = (const float*)d_in[0];
    float* out = (float*)d_out;
    fft1024_kernel<<<BATCH / (2 * PPB), TPB>>>(x, out);
}